// round 15
// baseline (speedup 1.0000x reference)
#include <cuda_runtime.h>
#include <cuda_fp16.h>
#include <cstdint>

// Problem constants
#define BSZ 4
#define LEN 2048
#define NH  12
#define HD  64
#define RR  16
#define HID 768
#define MM  (BSZ*LEN)   // 8192
#define NN  (NH*HD)     // 768
#define KK  HID         // 768

// ---------------------------------------------------------------------------
// Scratch (__device__ globals; allocation is forbidden)
// ---------------------------------------------------------------------------
__device__ __align__(16) __half g_Ahi[(size_t)MM * KK];
__device__ __align__(16) __half g_Alo[(size_t)MM * KK];
__device__ __align__(16) __half g_WhiK[(size_t)NN * KK];   // [n][k]
__device__ __align__(16) __half g_WloK[(size_t)NN * KK];
__device__ __align__(16) __half g_WhiV[(size_t)NN * KK];
__device__ __align__(16) __half g_WloV[(size_t)NN * KK];
__device__ __align__(16) __half g_V1[(size_t)MM * NN];     // fp16 V1
__device__ __align__(16) float g_dot[(size_t)MM * NH];
// Compact mask representation (scalar access ONLY)
__device__ int g_cnt[(size_t)BSZ * NH * LEN];
__device__ int g_e[(size_t)BSZ * NH * LEN];
__device__ int g_E[BSZ * NH];

// ---------------------------------------------------------------------------
// Baseline-PTX helpers (sm_80+: mma.sync / ldmatrix / cp.async — NO tcgen05)
// ---------------------------------------------------------------------------
__device__ __forceinline__ uint32_t smem_u32(const void* p) {
    uint32_t a;
    asm("{ .reg .u64 t; cvta.to.shared.u64 t, %1; cvt.u32.u64 %0, t; }"
        : "=r"(a) : "l"(p));
    return a;
}

__device__ __forceinline__ void cp16(uint32_t dst, const void* src) {
    asm volatile("cp.async.cg.shared.global [%0], [%1], 16;"
                 :: "r"(dst), "l"(src));
}
__device__ __forceinline__ void cp_commit() {
    asm volatile("cp.async.commit_group;");
}
template<int N> __device__ __forceinline__ void cp_wait() {
    asm volatile("cp.async.wait_group %0;" :: "n"(N));
}

__device__ __forceinline__ void ldsm4(uint32_t* r, uint32_t addr) {
    asm volatile("ldmatrix.sync.aligned.m8n8.x4.shared.b16 {%0,%1,%2,%3}, [%4];"
                 : "=r"(r[0]), "=r"(r[1]), "=r"(r[2]), "=r"(r[3]) : "r"(addr));
}

__device__ __forceinline__ void mma16816(float* c, const uint32_t* a,
                                         uint32_t b0, uint32_t b1) {
    asm volatile(
        "mma.sync.aligned.m16n8k16.row.col.f32.f16.f16.f32 "
        "{%0,%1,%2,%3}, {%4,%5,%6,%7}, {%8,%9}, {%0,%1,%2,%3};"
        : "+f"(c[0]), "+f"(c[1]), "+f"(c[2]), "+f"(c[3])
        : "r"(a[0]), "r"(a[1]), "r"(a[2]), "r"(a[3]), "r"(b0), "r"(b1));
}

// XOR-swizzled smem address: 128B rows, 16B segments, seg ^= (row & 7)
__device__ __forceinline__ uint32_t swz(int row, int seg) {
    return (uint32_t)(row * 128 + (((seg) ^ (row & 7)) << 4));
}

// ---------------------------------------------------------------------------
// Split-conversion kernels (fp32 -> fp16 hi + fp16 lo)
// ---------------------------------------------------------------------------
__device__ __forceinline__ uint32_t pack_h2(__half a, __half b) {
    return ((uint32_t)__half_as_ushort(b) << 16) | (uint32_t)__half_as_ushort(a);
}

__global__ __launch_bounds__(256) void convA_kernel(const float* __restrict__ A) {
    size_t i = ((size_t)blockIdx.x * 256 + threadIdx.x) * 4;
    float4 v = *(const float4*)(A + i);
    __half h0 = __float2half(v.x), h1 = __float2half(v.y);
    __half h2 = __float2half(v.z), h3 = __float2half(v.w);
    __half l0 = __float2half(v.x - __half2float(h0));
    __half l1 = __float2half(v.y - __half2float(h1));
    __half l2 = __float2half(v.z - __half2float(h2));
    __half l3 = __float2half(v.w - __half2float(h3));
    uint2 ph = make_uint2(pack_h2(h0, h1), pack_h2(h2, h3));
    uint2 pl = make_uint2(pack_h2(l0, l1), pack_h2(l2, l3));
    *(uint2*)((char*)g_Ahi + i * 2) = ph;
    *(uint2*)((char*)g_Alo + i * 2) = pl;
}

// Transpose W [k][n] -> [n][k], split hi/lo. blockIdx.z: 0 -> K, 1 -> V.
__global__ void convW_kernel(const float* __restrict__ WK,
                             const float* __restrict__ WV) {
    __shared__ float t[32][33];
    const float* W = (blockIdx.z == 0) ? WK : WV;
    int bx = blockIdx.x * 32;  // n tile
    int by = blockIdx.y * 32;  // k tile
    int tx = threadIdx.x, ty = threadIdx.y;
#pragma unroll
    for (int j = 0; j < 4; j++) {
        int r = ty + j * 8;
        t[r][tx] = W[(size_t)(by + r) * NN + bx + tx];
    }
    __syncthreads();
#pragma unroll
    for (int j = 0; j < 4; j++) {
        int r = ty + j * 8;
        float x = t[tx][r];  // = W[by+tx][bx+r]
        __half h = __float2half(x);
        __half l = __float2half(x - __half2float(h));
        size_t o = (size_t)(bx + r) * KK + by + tx;
        if (blockIdx.z == 0) { g_WhiK[o] = h; g_WloK[o] = l; }
        else                 { g_WhiV[o] = h; g_WloV[o] = l; }
    }
}

// ---------------------------------------------------------------------------
// FUSED mma.sync GEMM, fp16 3-pass split, 3 CTAs/SM version:
// BM=64, BN=128 (cols 0-63 = K head, 64-127 = V head), BK=32.
// hi/lo PACKED in one 128B smem row: segs 0-3 = hi, segs 4-7 = lo.
// Stage = A 8KB + B 16KB = 24KB; NSTAGE=3 -> 72KB/CTA -> 3 CTAs/SM.
// 256 threads = 8 warps (2m x 4n), warp tile 32x32. One barrier per chunk
// (3-stage pattern proven in R9). __launch_bounds__(256,3) caps regs ~85.
// ---------------------------------------------------------------------------
#define OFF_A  0
#define OFF_B  8192
#define STAGE  24576
#define NSTAGE 3
#define SM_TOTAL (NSTAGE * STAGE)   // 72 KB
#define NCHUNK (KK / 32)            // 24

__global__ __launch_bounds__(256, 3) void fused_gemm_kernel(
    const float* __restrict__ Kb, const float* __restrict__ Vb,
    const float* __restrict__ RH)
{
    extern __shared__ char smem[];
    __shared__ float sdot[64];
    const uint32_t sb = smem_u32(smem);

    const int tid = threadIdx.x;
    const int lane = tid & 31;
    const int wid = tid >> 5;
    const int nw = wid & 3;   // n warp col (0-1: K head, 2-3: V head)
    const int mw = wid >> 2;  // m warp row (0-1, 32 rows each)

    const int head = blockIdx.x;
    const int n0 = head * 64;
    const int m0 = blockIdx.y * 64;

    if (tid < 64) sdot[tid] = 0.f;

    float acc[2][4][4];
#pragma unroll
    for (int i = 0; i < 2; i++)
#pragma unroll
        for (int j = 0; j < 4; j++)
#pragma unroll
            for (int q = 0; q < 4; q++) acc[i][j][q] = 0.f;

    auto load_chunk = [&](int c) {
        if (c < NCHUNK) {
            const int kt = c * 32;
            const uint32_t stb = sb + (c % NSTAGE) * STAGE;
            // A: 64 rows x 8 segs (segs 0-3 hi, 4-7 lo), 512 positions
#pragma unroll
            for (int i = 0; i < 2; i++) {
                int p = tid + i * 256;
                int row = p >> 3, seg = p & 7;
                uint32_t so = swz(row, seg);
                const __half* src = (seg < 4) ? g_Ahi : g_Alo;
                cp16(stb + OFF_A + so,
                     src + (size_t)(m0 + row) * KK + kt + (seg & 3) * 8);
            }
            // B: 128 rows (0-63 K, 64-127 V) x 8 segs (0-3 hi, 4-7 lo)
#pragma unroll
            for (int i = 0; i < 4; i++) {
                int p = tid + i * 256;
                int row = p >> 3, seg = p & 7;
                uint32_t so = swz(row, seg);
                const __half* src;
                int grow;
                if (row < 64) {
                    src = (seg < 4) ? g_WhiK : g_WloK;
                    grow = n0 + row;
                } else {
                    src = (seg < 4) ? g_WhiV : g_WloV;
                    grow = n0 + row - 64;
                }
                cp16(stb + OFF_B + so,
                     src + (size_t)grow * KK + kt + (seg & 3) * 8);
            }
        }
        cp_commit();
    };

    load_chunk(0);
    load_chunk(1);

    for (int c = 0; c < NCHUNK; c++) {
        cp_wait<1>();
        __syncthreads();            // stage c visible; all warps done with c-1
        load_chunk(c + 2);          // overwrites stage (c-1)%3: safe (R9 pattern)

        const uint32_t stb = sb + (c % NSTAGE) * STAGE;
#pragma unroll
        for (int ks = 0; ks < 2; ks++) {
            uint32_t ah[2][4], al[2][4], bh[2][4], bl[2][4];
#pragma unroll
            for (int mi = 0; mi < 2; mi++) {
                int row = mw * 32 + mi * 16 + (lane & 15);
                int seg = ks * 2 + (lane >> 4);        // 0..3 (hi)
                ldsm4(ah[mi], stb + OFF_A + swz(row, seg));
                ldsm4(al[mi], stb + OFF_A + swz(row, seg + 4));
            }
#pragma unroll
            for (int nt = 0; nt < 2; nt++) {
                int row = nw * 32 + nt * 16 + (lane & 7) + ((lane >> 4) << 3);
                int seg = ks * 2 + ((lane >> 3) & 1);  // 0..3 (hi)
                ldsm4(bh[nt], stb + OFF_B + swz(row, seg));
                ldsm4(bl[nt], stb + OFF_B + swz(row, seg + 4));
            }
            // Pass-major: 8 independent HMMAs per pass
#pragma unroll
            for (int mi = 0; mi < 2; mi++)
#pragma unroll
                for (int nj = 0; nj < 4; nj++) {
                    const int nt = nj >> 1, rb = (nj & 1) * 2;
                    mma16816(acc[mi][nj], ah[mi], bh[nt][rb], bh[nt][rb + 1]);
                }
#pragma unroll
            for (int mi = 0; mi < 2; mi++)
#pragma unroll
                for (int nj = 0; nj < 4; nj++) {
                    const int nt = nj >> 1, rb = (nj & 1) * 2;
                    mma16816(acc[mi][nj], al[mi], bh[nt][rb], bh[nt][rb + 1]);
                }
#pragma unroll
            for (int mi = 0; mi < 2; mi++)
#pragma unroll
                for (int nj = 0; nj < 4; nj++) {
                    const int nt = nj >> 1, rb = (nj & 1) * 2;
                    mma16816(acc[mi][nj], ah[mi], bl[nt][rb], bl[nt][rb + 1]);
                }
        }
        // no trailing barrier: 3-stage + leading barrier covers reuse
    }

    // ---- epilogue ----
    const int rrow = lane >> 2;
    const int cq = (lane & 3) * 2;
    __syncthreads();

    if (nw < 2) {
#pragma unroll
        for (int mi = 0; mi < 2; mi++) {
            float s0 = 0.f, s1 = 0.f;
#pragma unroll
            for (int nj = 0; nj < 4; nj++) {
                const int n = n0 + nw * 32 + nj * 8 + cq;
                const float b0v = Kb[n], b1v = Kb[n + 1];
                const float rh0 = RH[n], rh1 = RH[n + 1];
                s0 += fmaxf(acc[mi][nj][0] + b0v, 0.f) * rh0
                    + fmaxf(acc[mi][nj][1] + b1v, 0.f) * rh1;
                s1 += fmaxf(acc[mi][nj][2] + b0v, 0.f) * rh0
                    + fmaxf(acc[mi][nj][3] + b1v, 0.f) * rh1;
            }
            s0 += __shfl_xor_sync(0xffffffffu, s0, 1);
            s0 += __shfl_xor_sync(0xffffffffu, s0, 2);
            s1 += __shfl_xor_sync(0xffffffffu, s1, 1);
            s1 += __shfl_xor_sync(0xffffffffu, s1, 2);
            if ((lane & 3) == 0) {
                atomicAdd(&sdot[mw * 32 + mi * 16 + rrow], s0);
                atomicAdd(&sdot[mw * 32 + mi * 16 + rrow + 8], s1);
            }
        }
    } else {
#pragma unroll
        for (int mi = 0; mi < 2; mi++) {
            const int r0 = m0 + mw * 32 + mi * 16 + rrow;
#pragma unroll
            for (int nj = 0; nj < 4; nj++) {
                const int n = n0 + (nw - 2) * 32 + nj * 8 + cq;
                const float b0v = Vb[n], b1v = Vb[n + 1];
                uint32_t p0 = pack_h2(__float2half(fmaxf(acc[mi][nj][0] + b0v, 0.f)),
                                      __float2half(fmaxf(acc[mi][nj][1] + b1v, 0.f)));
                uint32_t p1 = pack_h2(__float2half(fmaxf(acc[mi][nj][2] + b0v, 0.f)),
                                      __float2half(fmaxf(acc[mi][nj][3] + b1v, 0.f)));
                *(uint32_t*)&g_V1[(size_t)r0 * NN + n] = p0;
                *(uint32_t*)&g_V1[(size_t)(r0 + 8) * NN + n] = p1;
            }
        }
    }
    __syncthreads();
    if (tid < 64)
        g_dot[(size_t)(m0 + tid) * NH + head] = sdot[tid];
}

// ---------------------------------------------------------------------------
// Scan kernel (per (b,h)): prefix-count + event list -> compact cnt/e/E
// ---------------------------------------------------------------------------
__global__ __launch_bounds__(256) void scan_kernel()
{
    const int bh = blockIdx.x;
    const int b = bh / NH, h = bh % NH;

    __shared__ int s_cnt[LEN];
    __shared__ int s_e[LEN];
    __shared__ int s_wsum[8];

    const int tid = threadIdx.x;
    const int base = tid * 8;

    int c[8];
    unsigned mbits = 0;
    int run = 0;
#pragma unroll
    for (int q = 0; q < 8; q++) {
        int l = base + q;
        bool m = (l >= 1) && (g_dot[(size_t)(b * LEN + l) * NH + h] > 0.5f);
        if (m) { mbits |= 1u << q; run++; }
        c[q] = run;
    }

    const int lane = tid & 31, wd = tid >> 5;
    int v = run;
#pragma unroll
    for (int o = 1; o < 32; o <<= 1) {
        int nv = __shfl_up_sync(0xffffffffu, v, o);
        if (lane >= o) v += nv;
    }
    if (lane == 31) s_wsum[wd] = v;
    __syncthreads();
    int wpre = 0;
    for (int w = 0; w < wd; w++) wpre += s_wsum[w];
    const int excl = wpre + v - run;

#pragma unroll
    for (int q = 0; q < 8; q++) {
        s_cnt[base + q] = excl + c[q];
        if (mbits & (1u << q)) s_e[excl + c[q] - 1] = base + q;
    }
    __syncthreads();

    const int E = s_cnt[LEN - 1];
    if (tid == 0) g_E[bh] = E;

    for (int l = tid; l < LEN; l += 256)
        g_cnt[(size_t)bh * LEN + l] = s_cnt[l];
    for (int j = tid; j < E; j += 256)
        g_e[(size_t)bh * LEN + j] = s_e[j];
}

// ---------------------------------------------------------------------------
// Gather + weighted sum over fp16 V1, indices reconstructed from cnt/e.
// Block = (b,h) x 16 consecutive l; 16 threads/tuple; shfl-broadcast per r.
// ---------------------------------------------------------------------------
__global__ __launch_bounds__(256) void gather_kernel(
    const float* __restrict__ w, float* __restrict__ out)
{
    const int blk = blockIdx.x;
    const int bh = blk >> 7;             // / (LEN/16 = 128)
    const int l  = ((blk & 127) << 4) + (threadIdx.x >> 4);
    const int b = bh / NH, h = bh % NH;
    const int t = (b * LEN + l) * NH + h;
    const int lane = threadIdx.x & 31;
    const int r0 = lane & 15;
    const int d4 = (lane & 15) * 4;

    const int* cntp = g_cnt + (size_t)bh * LEN;
    const int* ev = g_e + (size_t)bh * LEN;
    const int E = __ldg(&g_E[bh]);
    const int cl = __ldg(cntp + l);
    const int cp = (l > 0) ? __ldg(cntp + l - 1) : 0;

    const int myf = (cl > r0) ? __ldg(ev + cl - 1 - r0) : 0;
    const int myb = (l > 0 && cp + r0 < E) ? __ldg(ev + cp + r0) : 0;
    const float mwf = __ldg(&w[h * 2 * RR + r0]);
    const float mwb = __ldg(&w[h * 2 * RR + RR + r0]);

    const __half* vb = g_V1 + (size_t)b * LEN * NN + h * HD + d4;

    float ax = 0.f, ay = 0.f, az = 0.f, aw = 0.f;
#pragma unroll
    for (int r = 0; r < RR; r++) {
        const int src = (lane & 16) | r;
        int i1 = __shfl_sync(0xffffffffu, myf, src);
        int i2 = __shfl_sync(0xffffffffu, myb, src);
        float w1 = __shfl_sync(0xffffffffu, mwf, src);
        float w2 = __shfl_sync(0xffffffffu, mwb, src);
        uint2 p1 = *(const uint2*)(vb + (size_t)i1 * NN);
        uint2 p2 = *(const uint2*)(vb + (size_t)i2 * NN);
        float2 a01 = __half22float2(*(const __half2*)&p1.x);
        float2 a23 = __half22float2(*(const __half2*)&p1.y);
        float2 b01 = __half22float2(*(const __half2*)&p2.x);
        float2 b23 = __half22float2(*(const __half2*)&p2.y);
        ax = fmaf(w1, a01.x, fmaf(w2, b01.x, ax));
        ay = fmaf(w1, a01.y, fmaf(w2, b01.y, ay));
        az = fmaf(w1, a23.x, fmaf(w2, b23.x, az));
        aw = fmaf(w1, a23.y, fmaf(w2, b23.y, aw));
    }
    *(float4*)(out + (size_t)t * HD + d4) = make_float4(ax, ay, az, aw);
}

// ---------------------------------------------------------------------------
extern "C" void kernel_launch(void* const* d_in, const int* in_sizes, int n_in,
                              void* d_out, int out_size)
{
    const float* hidden = (const float*)d_in[0];
    const float* K1w    = (const float*)d_in[1];
    const float* K1b    = (const float*)d_in[2];
    const float* V1w    = (const float*)d_in[3];
    const float* V1b    = (const float*)d_in[4];
    const float* RH     = (const float*)d_in[5];
    const float* bw     = (const float*)d_in[6];
    float* out = (float*)d_out;

    cudaFuncSetAttribute(fused_gemm_kernel,
                         cudaFuncAttributeMaxDynamicSharedMemorySize, SM_TOTAL);

    // 1) Split fp32 -> fp16 hi/lo (weights transposed to [n][k])
    convA_kernel<<<(MM * KK) / 1024, 256>>>(hidden);
    {
        dim3 tg(NN / 32, KK / 32, 2), tb(32, 8);
        convW_kernel<<<tg, tb>>>(K1w, V1w);
    }

    // 2) Fused tensor-core GEMM, BK=32 packed hi/lo, 3 CTAs/SM
    {
        dim3 gg(NH, MM / 64);  // (12, 128) = 1536 CTAs
        fused_gemm_kernel<<<gg, 256, SM_TOTAL>>>(K1b, V1b, RH);
    }

    // 3) Mask scan -> compact cnt/e/E
    scan_kernel<<<BSZ * NH, 256>>>();

    // 4) Gather + weighted sum
    gather_kernel<<<BSZ * NH * (LEN / 16), 256>>>(bw, out);
}

// round 16
// speedup vs baseline: 1.1965x; 1.1965x over previous
#include <cuda_runtime.h>
#include <cuda_fp16.h>
#include <cstdint>

// Problem constants
#define BSZ 4
#define LEN 2048
#define NH  12
#define HD  64
#define RR  16
#define HID 768
#define MM  (BSZ*LEN)   // 8192
#define NN  (NH*HD)     // 768
#define KK  HID         // 768

// ---------------------------------------------------------------------------
// Scratch (__device__ globals; allocation is forbidden)
// ---------------------------------------------------------------------------
__device__ __align__(16) __half g_Ahi[(size_t)MM * KK];
__device__ __align__(16) __half g_Alo[(size_t)MM * KK];
__device__ __align__(16) __half g_WhiK[(size_t)NN * KK];   // [n][k]
__device__ __align__(16) __half g_WloK[(size_t)NN * KK];
__device__ __align__(16) __half g_WhiV[(size_t)NN * KK];
__device__ __align__(16) __half g_WloV[(size_t)NN * KK];
__device__ __align__(16) __half g_V1[(size_t)MM * NN];     // fp16 V1
__device__ __align__(16) float g_dot[(size_t)MM * NH];
// Compact mask representation (scalar access ONLY)
__device__ int g_cnt[(size_t)BSZ * NH * LEN];
__device__ int g_e[(size_t)BSZ * NH * LEN];
__device__ int g_E[BSZ * NH];

// ---------------------------------------------------------------------------
// Baseline-PTX helpers (sm_80+: mma.sync / ldmatrix / cp.async — NO tcgen05)
// ---------------------------------------------------------------------------
__device__ __forceinline__ uint32_t smem_u32(const void* p) {
    uint32_t a;
    asm("{ .reg .u64 t; cvta.to.shared.u64 t, %1; cvt.u32.u64 %0, t; }"
        : "=r"(a) : "l"(p));
    return a;
}

__device__ __forceinline__ void cp16(uint32_t dst, const void* src) {
    asm volatile("cp.async.cg.shared.global [%0], [%1], 16;"
                 :: "r"(dst), "l"(src));
}
__device__ __forceinline__ void cp_commit() {
    asm volatile("cp.async.commit_group;");
}
template<int N> __device__ __forceinline__ void cp_wait() {
    asm volatile("cp.async.wait_group %0;" :: "n"(N));
}

__device__ __forceinline__ void ldsm4(uint32_t* r, uint32_t addr) {
    asm volatile("ldmatrix.sync.aligned.m8n8.x4.shared.b16 {%0,%1,%2,%3}, [%4];"
                 : "=r"(r[0]), "=r"(r[1]), "=r"(r[2]), "=r"(r[3]) : "r"(addr));
}

__device__ __forceinline__ void mma16816(float* c, const uint32_t* a,
                                         uint32_t b0, uint32_t b1) {
    asm volatile(
        "mma.sync.aligned.m16n8k16.row.col.f32.f16.f16.f32 "
        "{%0,%1,%2,%3}, {%4,%5,%6,%7}, {%8,%9}, {%0,%1,%2,%3};"
        : "+f"(c[0]), "+f"(c[1]), "+f"(c[2]), "+f"(c[3])
        : "r"(a[0]), "r"(a[1]), "r"(a[2]), "r"(a[3]), "r"(b0), "r"(b1));
}

// XOR-swizzled smem address: 128B rows, 16B segments, seg ^= (row & 7)
__device__ __forceinline__ uint32_t swz(int row, int seg) {
    return (uint32_t)(row * 128 + (((seg) ^ (row & 7)) << 4));
}

// ---------------------------------------------------------------------------
// Split-conversion kernels (fp32 -> fp16 hi + fp16 lo)
// ---------------------------------------------------------------------------
__device__ __forceinline__ uint32_t pack_h2(__half a, __half b) {
    return ((uint32_t)__half_as_ushort(b) << 16) | (uint32_t)__half_as_ushort(a);
}

// 8 floats per thread (two float4 reads, two uint2 writes per array)
__global__ __launch_bounds__(256) void convA_kernel(const float* __restrict__ A) {
    size_t i = ((size_t)blockIdx.x * 256 + threadIdx.x) * 8;
#pragma unroll
    for (int s = 0; s < 2; s++) {
        float4 v = *(const float4*)(A + i + s * 4);
        __half h0 = __float2half(v.x), h1 = __float2half(v.y);
        __half h2 = __float2half(v.z), h3 = __float2half(v.w);
        __half l0 = __float2half(v.x - __half2float(h0));
        __half l1 = __float2half(v.y - __half2float(h1));
        __half l2 = __float2half(v.z - __half2float(h2));
        __half l3 = __float2half(v.w - __half2float(h3));
        uint2 ph = make_uint2(pack_h2(h0, h1), pack_h2(h2, h3));
        uint2 pl = make_uint2(pack_h2(l0, l1), pack_h2(l2, l3));
        *(uint2*)((char*)g_Ahi + (i + s * 4) * 2) = ph;
        *(uint2*)((char*)g_Alo + (i + s * 4) * 2) = pl;
    }
}

// Transpose W [k][n] -> [n][k], split hi/lo. blockIdx.z: 0 -> K, 1 -> V.
__global__ void convW_kernel(const float* __restrict__ WK,
                             const float* __restrict__ WV) {
    __shared__ float t[32][33];
    const float* W = (blockIdx.z == 0) ? WK : WV;
    int bx = blockIdx.x * 32;  // n tile
    int by = blockIdx.y * 32;  // k tile
    int tx = threadIdx.x, ty = threadIdx.y;
#pragma unroll
    for (int j = 0; j < 4; j++) {
        int r = ty + j * 8;
        t[r][tx] = W[(size_t)(by + r) * NN + bx + tx];
    }
    __syncthreads();
#pragma unroll
    for (int j = 0; j < 4; j++) {
        int r = ty + j * 8;
        float x = t[tx][r];  // = W[by+tx][bx+r]
        __half h = __float2half(x);
        __half l = __float2half(x - __half2float(h));
        size_t o = (size_t)(bx + r) * KK + by + tx;
        if (blockIdx.z == 0) { g_WhiK[o] = h; g_WloK[o] = l; }
        else                 { g_WhiV[o] = h; g_WloV[o] = l; }
    }
}

// ---------------------------------------------------------------------------
// FUSED mma.sync GEMM, fp16 3-pass split — EXACT R14 config (135.4 us):
// BM=64, BN=128 (cols 0-63 = K head, 64-127 = V head), BK=64.
// 256 threads = 8 warps (2m x 4n), warp tile 32x32.
// 2-stage double buffer, 96KB/CTA -> 2 CTAs/SM. fp16 V1 store.
// Only the K-dot epilogue changed: non-atomic two-bank sdot.
// ---------------------------------------------------------------------------
#define OFF_AH 0
#define OFF_AL 8192
#define OFF_BH 16384
#define OFF_BL 32768
#define STAGE  49152
#define NSTAGE 2
#define SM_TOTAL (NSTAGE * STAGE)   // 96 KB
#define NCHUNK (KK / 64)            // 12

__global__ __launch_bounds__(256, 2) void fused_gemm_kernel(
    const float* __restrict__ Kb, const float* __restrict__ Vb,
    const float* __restrict__ RH)
{
    extern __shared__ char smem[];
    __shared__ float sdot[2][64];        // [nw bank][row] — no atomics
    const uint32_t sb = smem_u32(smem);

    const int tid = threadIdx.x;
    const int lane = tid & 31;
    const int wid = tid >> 5;
    const int nw = wid & 3;   // n warp col (0-1: K head, 2-3: V head)
    const int mw = wid >> 2;  // m warp row (0-1, 32 rows each)

    const int head = blockIdx.x;
    const int n0 = head * 64;
    const int m0 = blockIdx.y * 64;

    float acc[2][4][4];
#pragma unroll
    for (int i = 0; i < 2; i++)
#pragma unroll
        for (int j = 0; j < 4; j++)
#pragma unroll
            for (int q = 0; q < 4; q++) acc[i][j][q] = 0.f;

    auto load_chunk = [&](int c) {
        if (c < NCHUNK) {
            const int kt = c * 64;
            const uint32_t stb = sb + (c & 1) * STAGE;
#pragma unroll
            for (int i = 0; i < 2; i++) {
                int p = tid + i * 256;
                int row = p >> 3, seg = p & 7;
                uint32_t so = swz(row, seg);
                size_t ga = (size_t)(m0 + row) * KK + kt + seg * 8;
                cp16(stb + OFF_AH + so, g_Ahi + ga);
                cp16(stb + OFF_AL + so, g_Alo + ga);
            }
#pragma unroll
            for (int i = 0; i < 4; i++) {
                int p = tid + i * 256;
                int row = p >> 3, seg = p & 7;
                uint32_t so = swz(row, seg);
                const __half* bh;
                const __half* bl;
                int grow;
                if (row < 64) { bh = g_WhiK; bl = g_WloK; grow = n0 + row; }
                else          { bh = g_WhiV; bl = g_WloV; grow = n0 + row - 64; }
                size_t gb = (size_t)grow * KK + kt + seg * 8;
                cp16(stb + OFF_BH + so, bh + gb);
                cp16(stb + OFF_BL + so, bl + gb);
            }
        }
        cp_commit();
    };

    load_chunk(0);

    for (int c = 0; c < NCHUNK; c++) {
        load_chunk(c + 1);
        cp_wait<1>();
        __syncthreads();

        const uint32_t stb = sb + (c & 1) * STAGE;
#pragma unroll
        for (int ks = 0; ks < 4; ks++) {
            uint32_t ah[2][4], al[2][4], bh[2][4], bl[2][4];
#pragma unroll
            for (int mi = 0; mi < 2; mi++) {
                int row = mw * 32 + mi * 16 + (lane & 15);
                int seg = ks * 2 + (lane >> 4);
                uint32_t ao = swz(row, seg);
                ldsm4(ah[mi], stb + OFF_AH + ao);
                ldsm4(al[mi], stb + OFF_AL + ao);
            }
#pragma unroll
            for (int nt = 0; nt < 2; nt++) {
                int row = nw * 32 + nt * 16 + (lane & 7) + ((lane >> 4) << 3);
                int seg = ks * 2 + ((lane >> 3) & 1);
                uint32_t bo = swz(row, seg);
                ldsm4(bh[nt], stb + OFF_BH + bo);
                ldsm4(bl[nt], stb + OFF_BL + bo);
            }
#pragma unroll
            for (int mi = 0; mi < 2; mi++)
#pragma unroll
                for (int nj = 0; nj < 4; nj++) {
                    const int nt = nj >> 1, rb = (nj & 1) * 2;
                    mma16816(acc[mi][nj], ah[mi], bh[nt][rb], bh[nt][rb + 1]);
                }
#pragma unroll
            for (int mi = 0; mi < 2; mi++)
#pragma unroll
                for (int nj = 0; nj < 4; nj++) {
                    const int nt = nj >> 1, rb = (nj & 1) * 2;
                    mma16816(acc[mi][nj], al[mi], bh[nt][rb], bh[nt][rb + 1]);
                }
#pragma unroll
            for (int mi = 0; mi < 2; mi++)
#pragma unroll
                for (int nj = 0; nj < 4; nj++) {
                    const int nt = nj >> 1, rb = (nj & 1) * 2;
                    mma16816(acc[mi][nj], ah[mi], bl[nt][rb], bl[nt][rb + 1]);
                }
        }
        __syncthreads();
    }

    // ---- epilogue ----
    const int rrow = lane >> 2;
    const int cq = (lane & 3) * 2;

    if (nw < 2) {
        // K path: dot(relu(K1 + Kb), RH) per row; each (mw,nw) warp owns
        // rows [mw*32, mw*32+32) x bank nw — lanes (lane&3)==0 write disjoint
        // sdot[nw][row] entries (no atomics needed).
#pragma unroll
        for (int mi = 0; mi < 2; mi++) {
            float s0 = 0.f, s1 = 0.f;
#pragma unroll
            for (int nj = 0; nj < 4; nj++) {
                const int n = n0 + nw * 32 + nj * 8 + cq;
                const float b0v = Kb[n], b1v = Kb[n + 1];
                const float rh0 = RH[n], rh1 = RH[n + 1];
                s0 += fmaxf(acc[mi][nj][0] + b0v, 0.f) * rh0
                    + fmaxf(acc[mi][nj][1] + b1v, 0.f) * rh1;
                s1 += fmaxf(acc[mi][nj][2] + b0v, 0.f) * rh0
                    + fmaxf(acc[mi][nj][3] + b1v, 0.f) * rh1;
            }
            s0 += __shfl_xor_sync(0xffffffffu, s0, 1);
            s0 += __shfl_xor_sync(0xffffffffu, s0, 2);
            s1 += __shfl_xor_sync(0xffffffffu, s1, 1);
            s1 += __shfl_xor_sync(0xffffffffu, s1, 2);
            if ((lane & 3) == 0) {
                sdot[nw][mw * 32 + mi * 16 + rrow] = s0;
                sdot[nw][mw * 32 + mi * 16 + rrow + 8] = s1;
            }
        }
    } else {
        // V path: store relu(V1 + Vb) as fp16
#pragma unroll
        for (int mi = 0; mi < 2; mi++) {
            const int r0 = m0 + mw * 32 + mi * 16 + rrow;
#pragma unroll
            for (int nj = 0; nj < 4; nj++) {
                const int n = n0 + (nw - 2) * 32 + nj * 8 + cq;
                const float b0v = Vb[n], b1v = Vb[n + 1];
                uint32_t p0 = pack_h2(__float2half(fmaxf(acc[mi][nj][0] + b0v, 0.f)),
                                      __float2half(fmaxf(acc[mi][nj][1] + b1v, 0.f)));
                uint32_t p1 = pack_h2(__float2half(fmaxf(acc[mi][nj][2] + b0v, 0.f)),
                                      __float2half(fmaxf(acc[mi][nj][3] + b1v, 0.f)));
                *(uint32_t*)&g_V1[(size_t)r0 * NN + n] = p0;
                *(uint32_t*)&g_V1[(size_t)(r0 + 8) * NN + n] = p1;
            }
        }
    }
    __syncthreads();
    if (tid < 64)
        g_dot[(size_t)(m0 + tid) * NH + head] = sdot[0][tid] + sdot[1][tid];
}

// ---------------------------------------------------------------------------
// Scan kernel (per (b,h)): prefix-count + event list -> compact cnt/e/E
// ---------------------------------------------------------------------------
__global__ __launch_bounds__(256) void scan_kernel()
{
    const int bh = blockIdx.x;
    const int b = bh / NH, h = bh % NH;

    __shared__ int s_cnt[LEN];
    __shared__ int s_e[LEN];
    __shared__ int s_wsum[8];

    const int tid = threadIdx.x;
    const int base = tid * 8;

    int c[8];
    unsigned mbits = 0;
    int run = 0;
#pragma unroll
    for (int q = 0; q < 8; q++) {
        int l = base + q;
        bool m = (l >= 1) && (g_dot[(size_t)(b * LEN + l) * NH + h] > 0.5f);
        if (m) { mbits |= 1u << q; run++; }
        c[q] = run;
    }

    const int lane = tid & 31, wd = tid >> 5;
    int v = run;
#pragma unroll
    for (int o = 1; o < 32; o <<= 1) {
        int nv = __shfl_up_sync(0xffffffffu, v, o);
        if (lane >= o) v += nv;
    }
    if (lane == 31) s_wsum[wd] = v;
    __syncthreads();
    int wpre = 0;
    for (int w = 0; w < wd; w++) wpre += s_wsum[w];
    const int excl = wpre + v - run;

#pragma unroll
    for (int q = 0; q < 8; q++) {
        s_cnt[base + q] = excl + c[q];
        if (mbits & (1u << q)) s_e[excl + c[q] - 1] = base + q;
    }
    __syncthreads();

    const int E = s_cnt[LEN - 1];
    if (tid == 0) g_E[bh] = E;

    for (int l = tid; l < LEN; l += 256)
        g_cnt[(size_t)bh * LEN + l] = s_cnt[l];
    for (int j = tid; j < E; j += 256)
        g_e[(size_t)bh * LEN + j] = s_e[j];
}

// ---------------------------------------------------------------------------
// Gather + weighted sum over fp16 V1, indices reconstructed from cnt/e.
// Block = (b,h) x 16 consecutive l; 16 threads/tuple; shfl-broadcast per r.
// ---------------------------------------------------------------------------
__global__ __launch_bounds__(256) void gather_kernel(
    const float* __restrict__ w, float* __restrict__ out)
{
    const int blk = blockIdx.x;
    const int bh = blk >> 7;             // / (LEN/16 = 128)
    const int l  = ((blk & 127) << 4) + (threadIdx.x >> 4);
    const int b = bh / NH, h = bh % NH;
    const int t = (b * LEN + l) * NH + h;
    const int lane = threadIdx.x & 31;
    const int r0 = lane & 15;
    const int d4 = (lane & 15) * 4;

    const int* cntp = g_cnt + (size_t)bh * LEN;
    const int* ev = g_e + (size_t)bh * LEN;
    const int E = __ldg(&g_E[bh]);
    const int cl = __ldg(cntp + l);
    const int cp = (l > 0) ? __ldg(cntp + l - 1) : 0;

    const int myf = (cl > r0) ? __ldg(ev + cl - 1 - r0) : 0;
    const int myb = (l > 0 && cp + r0 < E) ? __ldg(ev + cp + r0) : 0;
    const float mwf = __ldg(&w[h * 2 * RR + r0]);
    const float mwb = __ldg(&w[h * 2 * RR + RR + r0]);

    const __half* vb = g_V1 + (size_t)b * LEN * NN + h * HD + d4;

    float ax = 0.f, ay = 0.f, az = 0.f, aw = 0.f;
#pragma unroll
    for (int r = 0; r < RR; r++) {
        const int src = (lane & 16) | r;
        int i1 = __shfl_sync(0xffffffffu, myf, src);
        int i2 = __shfl_sync(0xffffffffu, myb, src);
        float w1 = __shfl_sync(0xffffffffu, mwf, src);
        float w2 = __shfl_sync(0xffffffffu, mwb, src);
        uint2 p1 = *(const uint2*)(vb + (size_t)i1 * NN);
        uint2 p2 = *(const uint2*)(vb + (size_t)i2 * NN);
        float2 a01 = __half22float2(*(const __half2*)&p1.x);
        float2 a23 = __half22float2(*(const __half2*)&p1.y);
        float2 b01 = __half22float2(*(const __half2*)&p2.x);
        float2 b23 = __half22float2(*(const __half2*)&p2.y);
        ax = fmaf(w1, a01.x, fmaf(w2, b01.x, ax));
        ay = fmaf(w1, a01.y, fmaf(w2, b01.y, ay));
        az = fmaf(w1, a23.x, fmaf(w2, b23.x, az));
        aw = fmaf(w1, a23.y, fmaf(w2, b23.y, aw));
    }
    *(float4*)(out + (size_t)t * HD + d4) = make_float4(ax, ay, az, aw);
}

// ---------------------------------------------------------------------------
extern "C" void kernel_launch(void* const* d_in, const int* in_sizes, int n_in,
                              void* d_out, int out_size)
{
    const float* hidden = (const float*)d_in[0];
    const float* K1w    = (const float*)d_in[1];
    const float* K1b    = (const float*)d_in[2];
    const float* V1w    = (const float*)d_in[3];
    const float* V1b    = (const float*)d_in[4];
    const float* RH     = (const float*)d_in[5];
    const float* bw     = (const float*)d_in[6];
    float* out = (float*)d_out;

    cudaFuncSetAttribute(fused_gemm_kernel,
                         cudaFuncAttributeMaxDynamicSharedMemorySize, SM_TOTAL);

    // 1) Split fp32 -> fp16 hi/lo (weights transposed to [n][k])
    convA_kernel<<<(MM * KK) / 2048, 256>>>(hidden);
    {
        dim3 tg(NN / 32, KK / 32, 2), tb(32, 8);
        convW_kernel<<<tg, tb>>>(K1w, V1w);
    }

    // 2) Fused tensor-core GEMM (R14 config, non-atomic K epilogue)
    {
        dim3 gg(NH, MM / 64);  // (12, 128) = 1536 CTAs
        fused_gemm_kernel<<<gg, 256, SM_TOTAL>>>(K1b, V1b, RH);
    }

    // 3) Mask scan -> compact cnt/e/E
    scan_kernel<<<BSZ * NH, 256>>>();

    // 4) Gather + weighted sum
    gather_kernel<<<BSZ * NH * (LEN / 16), 256>>>(bw, out);
}

// round 17
// speedup vs baseline: 1.2538x; 1.0479x over previous
#include <cuda_runtime.h>
#include <cuda_fp16.h>
#include <cstdint>

// Problem constants
#define BSZ 4
#define LEN 2048
#define NH  12
#define HD  64
#define RR  16
#define HID 768
#define MM  (BSZ*LEN)   // 8192
#define NN  (NH*HD)     // 768
#define KK  HID         // 768

// ---------------------------------------------------------------------------
// Scratch (__device__ globals; allocation is forbidden)
// ---------------------------------------------------------------------------
__device__ __align__(16) __half g_Ahi[(size_t)MM * KK];
__device__ __align__(16) __half g_Alo[(size_t)MM * KK];
__device__ __align__(16) __half g_WhiK[(size_t)NN * KK];   // [n][k]
__device__ __align__(16) __half g_WloK[(size_t)NN * KK];
__device__ __align__(16) __half g_WhiV[(size_t)NN * KK];
__device__ __align__(16) __half g_WloV[(size_t)NN * KK];
__device__ __align__(16) __half g_V1[(size_t)MM * NN];     // fp16 V1
__device__ __align__(16) float g_dot[(size_t)MM * NH];
// Compact mask representation (scalar access ONLY)
__device__ int g_cnt[(size_t)BSZ * NH * LEN];
__device__ int g_e[(size_t)BSZ * NH * LEN];
__device__ int g_E[BSZ * NH];

// ---------------------------------------------------------------------------
// Baseline-PTX helpers (sm_80+: mma.sync / ldmatrix / cp.async — NO tcgen05)
// ---------------------------------------------------------------------------
__device__ __forceinline__ uint32_t smem_u32(const void* p) {
    uint32_t a;
    asm("{ .reg .u64 t; cvta.to.shared.u64 t, %1; cvt.u32.u64 %0, t; }"
        : "=r"(a) : "l"(p));
    return a;
}

__device__ __forceinline__ void cp16(uint32_t dst, const void* src) {
    asm volatile("cp.async.cg.shared.global [%0], [%1], 16;"
                 :: "r"(dst), "l"(src));
}
__device__ __forceinline__ void cp_commit() {
    asm volatile("cp.async.commit_group;");
}
template<int N> __device__ __forceinline__ void cp_wait() {
    asm volatile("cp.async.wait_group %0;" :: "n"(N));
}

__device__ __forceinline__ void ldsm4(uint32_t* r, uint32_t addr) {
    asm volatile("ldmatrix.sync.aligned.m8n8.x4.shared.b16 {%0,%1,%2,%3}, [%4];"
                 : "=r"(r[0]), "=r"(r[1]), "=r"(r[2]), "=r"(r[3]) : "r"(addr));
}

__device__ __forceinline__ void mma16816(float* c, const uint32_t* a,
                                         uint32_t b0, uint32_t b1) {
    asm volatile(
        "mma.sync.aligned.m16n8k16.row.col.f32.f16.f16.f32 "
        "{%0,%1,%2,%3}, {%4,%5,%6,%7}, {%8,%9}, {%0,%1,%2,%3};"
        : "+f"(c[0]), "+f"(c[1]), "+f"(c[2]), "+f"(c[3])
        : "r"(a[0]), "r"(a[1]), "r"(a[2]), "r"(a[3]), "r"(b0), "r"(b1));
}

// XOR-swizzled smem address: 128B rows, 16B segments, seg ^= (row & 7)
__device__ __forceinline__ uint32_t swz(int row, int seg) {
    return (uint32_t)(row * 128 + (((seg) ^ (row & 7)) << 4));
}

// ---------------------------------------------------------------------------
// Merged split-conversion kernel: blocks [0, NA) convert A (8 floats/thread),
// blocks [NA, NA+2*24*24) transpose+split W (K then V).
// Both parts use 256 threads.
// ---------------------------------------------------------------------------
#define NA_BLOCKS ((MM * KK) / 2048)          // 3072
#define NW_TILES  ((NN / 32) * (KK / 32))     // 576 per weight matrix

__device__ __forceinline__ uint32_t pack_h2(__half a, __half b) {
    return ((uint32_t)__half_as_ushort(b) << 16) | (uint32_t)__half_as_ushort(a);
}

__global__ __launch_bounds__(256) void conv_kernel(
    const float* __restrict__ A,
    const float* __restrict__ WK, const float* __restrict__ WV)
{
    const int tid = threadIdx.x;
    if (blockIdx.x < NA_BLOCKS) {
        // ---- A split: 8 floats per thread ----
        size_t i = ((size_t)blockIdx.x * 256 + tid) * 8;
#pragma unroll
        for (int s = 0; s < 2; s++) {
            float4 v = *(const float4*)(A + i + s * 4);
            __half h0 = __float2half(v.x), h1 = __float2half(v.y);
            __half h2 = __float2half(v.z), h3 = __float2half(v.w);
            __half l0 = __float2half(v.x - __half2float(h0));
            __half l1 = __float2half(v.y - __half2float(h1));
            __half l2 = __float2half(v.z - __half2float(h2));
            __half l3 = __float2half(v.w - __half2float(h3));
            uint2 ph = make_uint2(pack_h2(h0, h1), pack_h2(h2, h3));
            uint2 pl = make_uint2(pack_h2(l0, l1), pack_h2(l2, l3));
            *(uint2*)((char*)g_Ahi + (i + s * 4) * 2) = ph;
            *(uint2*)((char*)g_Alo + (i + s * 4) * 2) = pl;
        }
    } else {
        // ---- W transpose + split ----
        __shared__ float t[32][33];
        int wb = blockIdx.x - NA_BLOCKS;          // 0 .. 2*NW_TILES-1
        const int which = (wb >= NW_TILES) ? 1 : 0;
        if (which) wb -= NW_TILES;
        const float* W = which ? WV : WK;
        const int bx = (wb % (NN / 32)) * 32;     // n tile
        const int by = (wb / (NN / 32)) * 32;     // k tile
        const int tx = tid & 31, ty = tid >> 5;   // (32, 8)
#pragma unroll
        for (int j = 0; j < 4; j++) {
            int r = ty + j * 8;
            t[r][tx] = W[(size_t)(by + r) * NN + bx + tx];
        }
        __syncthreads();
#pragma unroll
        for (int j = 0; j < 4; j++) {
            int r = ty + j * 8;
            float x = t[tx][r];  // = W[by+tx][bx+r]
            __half h = __float2half(x);
            __half l = __float2half(x - __half2float(h));
            size_t o = (size_t)(bx + r) * KK + by + tx;
            if (which == 0) { g_WhiK[o] = h; g_WloK[o] = l; }
            else            { g_WhiV[o] = h; g_WloV[o] = l; }
        }
    }
}

// ---------------------------------------------------------------------------
// FUSED mma.sync GEMM, fp16 3-pass split — R14/R16 config (135.4 us):
// BM=64, BN=128 (cols 0-63 = K head, 64-127 = V head), BK=64.
// 256 threads = 8 warps (2m x 4n), warp tile 32x32.
// 2-stage double buffer, 96KB/CTA -> 2 CTAs/SM. fp16 V1 store.
// Non-atomic two-bank K-dot epilogue.
// ---------------------------------------------------------------------------
#define OFF_AH 0
#define OFF_AL 8192
#define OFF_BH 16384
#define OFF_BL 32768
#define STAGE  49152
#define NSTAGE 2
#define SM_TOTAL (NSTAGE * STAGE)   // 96 KB
#define NCHUNK (KK / 64)            // 12

__global__ __launch_bounds__(256, 2) void fused_gemm_kernel(
    const float* __restrict__ Kb, const float* __restrict__ Vb,
    const float* __restrict__ RH)
{
    extern __shared__ char smem[];
    __shared__ float sdot[2][64];
    const uint32_t sb = smem_u32(smem);

    const int tid = threadIdx.x;
    const int lane = tid & 31;
    const int wid = tid >> 5;
    const int nw = wid & 3;   // n warp col (0-1: K head, 2-3: V head)
    const int mw = wid >> 2;  // m warp row (0-1, 32 rows each)

    const int head = blockIdx.x;
    const int n0 = head * 64;
    const int m0 = blockIdx.y * 64;

    float acc[2][4][4];
#pragma unroll
    for (int i = 0; i < 2; i++)
#pragma unroll
        for (int j = 0; j < 4; j++)
#pragma unroll
            for (int q = 0; q < 4; q++) acc[i][j][q] = 0.f;

    auto load_chunk = [&](int c) {
        if (c < NCHUNK) {
            const int kt = c * 64;
            const uint32_t stb = sb + (c & 1) * STAGE;
#pragma unroll
            for (int i = 0; i < 2; i++) {
                int p = tid + i * 256;
                int row = p >> 3, seg = p & 7;
                uint32_t so = swz(row, seg);
                size_t ga = (size_t)(m0 + row) * KK + kt + seg * 8;
                cp16(stb + OFF_AH + so, g_Ahi + ga);
                cp16(stb + OFF_AL + so, g_Alo + ga);
            }
#pragma unroll
            for (int i = 0; i < 4; i++) {
                int p = tid + i * 256;
                int row = p >> 3, seg = p & 7;
                uint32_t so = swz(row, seg);
                const __half* bh;
                const __half* bl;
                int grow;
                if (row < 64) { bh = g_WhiK; bl = g_WloK; grow = n0 + row; }
                else          { bh = g_WhiV; bl = g_WloV; grow = n0 + row - 64; }
                size_t gb = (size_t)grow * KK + kt + seg * 8;
                cp16(stb + OFF_BH + so, bh + gb);
                cp16(stb + OFF_BL + so, bl + gb);
            }
        }
        cp_commit();
    };

    load_chunk(0);

    for (int c = 0; c < NCHUNK; c++) {
        load_chunk(c + 1);
        cp_wait<1>();
        __syncthreads();

        const uint32_t stb = sb + (c & 1) * STAGE;
#pragma unroll
        for (int ks = 0; ks < 4; ks++) {
            uint32_t ah[2][4], al[2][4], bh[2][4], bl[2][4];
#pragma unroll
            for (int mi = 0; mi < 2; mi++) {
                int row = mw * 32 + mi * 16 + (lane & 15);
                int seg = ks * 2 + (lane >> 4);
                uint32_t ao = swz(row, seg);
                ldsm4(ah[mi], stb + OFF_AH + ao);
                ldsm4(al[mi], stb + OFF_AL + ao);
            }
#pragma unroll
            for (int nt = 0; nt < 2; nt++) {
                int row = nw * 32 + nt * 16 + (lane & 7) + ((lane >> 4) << 3);
                int seg = ks * 2 + ((lane >> 3) & 1);
                uint32_t bo = swz(row, seg);
                ldsm4(bh[nt], stb + OFF_BH + bo);
                ldsm4(bl[nt], stb + OFF_BL + bo);
            }
#pragma unroll
            for (int mi = 0; mi < 2; mi++)
#pragma unroll
                for (int nj = 0; nj < 4; nj++) {
                    const int nt = nj >> 1, rb = (nj & 1) * 2;
                    mma16816(acc[mi][nj], ah[mi], bh[nt][rb], bh[nt][rb + 1]);
                }
#pragma unroll
            for (int mi = 0; mi < 2; mi++)
#pragma unroll
                for (int nj = 0; nj < 4; nj++) {
                    const int nt = nj >> 1, rb = (nj & 1) * 2;
                    mma16816(acc[mi][nj], al[mi], bh[nt][rb], bh[nt][rb + 1]);
                }
#pragma unroll
            for (int mi = 0; mi < 2; mi++)
#pragma unroll
                for (int nj = 0; nj < 4; nj++) {
                    const int nt = nj >> 1, rb = (nj & 1) * 2;
                    mma16816(acc[mi][nj], ah[mi], bl[nt][rb], bl[nt][rb + 1]);
                }
        }
        __syncthreads();
    }

    // ---- epilogue ----
    const int rrow = lane >> 2;
    const int cq = (lane & 3) * 2;

    if (nw < 2) {
#pragma unroll
        for (int mi = 0; mi < 2; mi++) {
            float s0 = 0.f, s1 = 0.f;
#pragma unroll
            for (int nj = 0; nj < 4; nj++) {
                const int n = n0 + nw * 32 + nj * 8 + cq;
                const float b0v = Kb[n], b1v = Kb[n + 1];
                const float rh0 = RH[n], rh1 = RH[n + 1];
                s0 += fmaxf(acc[mi][nj][0] + b0v, 0.f) * rh0
                    + fmaxf(acc[mi][nj][1] + b1v, 0.f) * rh1;
                s1 += fmaxf(acc[mi][nj][2] + b0v, 0.f) * rh0
                    + fmaxf(acc[mi][nj][3] + b1v, 0.f) * rh1;
            }
            s0 += __shfl_xor_sync(0xffffffffu, s0, 1);
            s0 += __shfl_xor_sync(0xffffffffu, s0, 2);
            s1 += __shfl_xor_sync(0xffffffffu, s1, 1);
            s1 += __shfl_xor_sync(0xffffffffu, s1, 2);
            if ((lane & 3) == 0) {
                sdot[nw][mw * 32 + mi * 16 + rrow] = s0;
                sdot[nw][mw * 32 + mi * 16 + rrow + 8] = s1;
            }
        }
    } else {
#pragma unroll
        for (int mi = 0; mi < 2; mi++) {
            const int r0 = m0 + mw * 32 + mi * 16 + rrow;
#pragma unroll
            for (int nj = 0; nj < 4; nj++) {
                const int n = n0 + (nw - 2) * 32 + nj * 8 + cq;
                const float b0v = Vb[n], b1v = Vb[n + 1];
                uint32_t p0 = pack_h2(__float2half(fmaxf(acc[mi][nj][0] + b0v, 0.f)),
                                      __float2half(fmaxf(acc[mi][nj][1] + b1v, 0.f)));
                uint32_t p1 = pack_h2(__float2half(fmaxf(acc[mi][nj][2] + b0v, 0.f)),
                                      __float2half(fmaxf(acc[mi][nj][3] + b1v, 0.f)));
                *(uint32_t*)&g_V1[(size_t)r0 * NN + n] = p0;
                *(uint32_t*)&g_V1[(size_t)(r0 + 8) * NN + n] = p1;
            }
        }
    }
    __syncthreads();
    if (tid < 64)
        g_dot[(size_t)(m0 + tid) * NH + head] = sdot[0][tid] + sdot[1][tid];
}

// ---------------------------------------------------------------------------
// Scan kernel (per (b,h)): prefix-count + event list -> compact cnt/e/E
// ---------------------------------------------------------------------------
__global__ __launch_bounds__(256) void scan_kernel()
{
    const int bh = blockIdx.x;
    const int b = bh / NH, h = bh % NH;

    __shared__ int s_cnt[LEN];
    __shared__ int s_e[LEN];
    __shared__ int s_wsum[8];

    const int tid = threadIdx.x;
    const int base = tid * 8;

    int c[8];
    unsigned mbits = 0;
    int run = 0;
#pragma unroll
    for (int q = 0; q < 8; q++) {
        int l = base + q;
        bool m = (l >= 1) && (g_dot[(size_t)(b * LEN + l) * NH + h] > 0.5f);
        if (m) { mbits |= 1u << q; run++; }
        c[q] = run;
    }

    const int lane = tid & 31, wd = tid >> 5;
    int v = run;
#pragma unroll
    for (int o = 1; o < 32; o <<= 1) {
        int nv = __shfl_up_sync(0xffffffffu, v, o);
        if (lane >= o) v += nv;
    }
    if (lane == 31) s_wsum[wd] = v;
    __syncthreads();
    int wpre = 0;
    for (int w = 0; w < wd; w++) wpre += s_wsum[w];
    const int excl = wpre + v - run;

#pragma unroll
    for (int q = 0; q < 8; q++) {
        s_cnt[base + q] = excl + c[q];
        if (mbits & (1u << q)) s_e[excl + c[q] - 1] = base + q;
    }
    __syncthreads();

    const int E = s_cnt[LEN - 1];
    if (tid == 0) g_E[bh] = E;

    for (int l = tid; l < LEN; l += 256)
        g_cnt[(size_t)bh * LEN + l] = s_cnt[l];
    for (int j = tid; j < E; j += 256)
        g_e[(size_t)bh * LEN + j] = s_e[j];
}

// ---------------------------------------------------------------------------
// Gather + weighted sum over fp16 V1, indices reconstructed from cnt/e.
// 8 threads per tuple (uint4 = 16B per gathered row per lane).
// Block = (b,h) x 32 consecutive l values (256 threads).
// Each lane preloads TWO (r, r+8) index/weight quartets; 8-lane groups
// broadcast via shfl.
// ---------------------------------------------------------------------------
__global__ __launch_bounds__(256) void gather_kernel(
    const float* __restrict__ w, float* __restrict__ out)
{
    const int blk = blockIdx.x;
    const int bh = blk >> 6;             // / (LEN/32 = 64)
    const int l  = ((blk & 63) << 5) + (threadIdx.x >> 3);
    const int b = bh / NH, h = bh % NH;
    const int t = (b * LEN + l) * NH + h;
    const int lane = threadIdx.x & 31;
    const int r0 = lane & 7;             // preloads r0 and r0+8
    const int d8 = (lane & 7) * 8;       // half index within head dim (8 halves)

    const int* cntp = g_cnt + (size_t)bh * LEN;
    const int* ev = g_e + (size_t)bh * LEN;
    const int E = __ldg(&g_E[bh]);
    const int cl = __ldg(cntp + l);
    const int cp = (l > 0) ? __ldg(cntp + l - 1) : 0;

    int myf[2], myb[2];
    float mwf[2], mwb[2];
#pragma unroll
    for (int s = 0; s < 2; s++) {
        const int r = r0 + s * 8;
        myf[s] = (cl > r) ? __ldg(ev + cl - 1 - r) : 0;
        myb[s] = (l > 0 && cp + r < E) ? __ldg(ev + cp + r) : 0;
        mwf[s] = __ldg(&w[h * 2 * RR + r]);
        mwb[s] = __ldg(&w[h * 2 * RR + RR + r]);
    }

    const __half* vb = g_V1 + (size_t)b * LEN * NN + h * HD + d8;

    float a0 = 0.f, a1 = 0.f, a2 = 0.f, a3 = 0.f;
    float a4 = 0.f, a5 = 0.f, a6 = 0.f, a7 = 0.f;
#pragma unroll
    for (int r = 0; r < RR; r++) {
        const int s = r >> 3;                     // which preload register
        const int src = (lane & 24) | (r & 7);    // same 8-lane group
        int i1 = __shfl_sync(0xffffffffu, myf[s], src);
        int i2 = __shfl_sync(0xffffffffu, myb[s], src);
        float w1 = __shfl_sync(0xffffffffu, mwf[s], src);
        float w2 = __shfl_sync(0xffffffffu, mwb[s], src);
        uint4 p1 = *(const uint4*)(vb + (size_t)i1 * NN);
        uint4 p2 = *(const uint4*)(vb + (size_t)i2 * NN);
        float2 f0 = __half22float2(*(const __half2*)&p1.x);
        float2 f1 = __half22float2(*(const __half2*)&p1.y);
        float2 f2 = __half22float2(*(const __half2*)&p1.z);
        float2 f3 = __half22float2(*(const __half2*)&p1.w);
        float2 g0 = __half22float2(*(const __half2*)&p2.x);
        float2 g1 = __half22float2(*(const __half2*)&p2.y);
        float2 g2 = __half22float2(*(const __half2*)&p2.z);
        float2 g3 = __half22float2(*(const __half2*)&p2.w);
        a0 = fmaf(w1, f0.x, fmaf(w2, g0.x, a0));
        a1 = fmaf(w1, f0.y, fmaf(w2, g0.y, a1));
        a2 = fmaf(w1, f1.x, fmaf(w2, g1.x, a2));
        a3 = fmaf(w1, f1.y, fmaf(w2, g1.y, a3));
        a4 = fmaf(w1, f2.x, fmaf(w2, g2.x, a4));
        a5 = fmaf(w1, f2.y, fmaf(w2, g2.y, a5));
        a6 = fmaf(w1, f3.x, fmaf(w2, g3.x, a6));
        a7 = fmaf(w1, f3.y, fmaf(w2, g3.y, a7));
    }
    float* op = out + (size_t)t * HD + d8;
    *(float4*)op = make_float4(a0, a1, a2, a3);
    *(float4*)(op + 4) = make_float4(a4, a5, a6, a7);
}

// ---------------------------------------------------------------------------
extern "C" void kernel_launch(void* const* d_in, const int* in_sizes, int n_in,
                              void* d_out, int out_size)
{
    const float* hidden = (const float*)d_in[0];
    const float* K1w    = (const float*)d_in[1];
    const float* K1b    = (const float*)d_in[2];
    const float* V1w    = (const float*)d_in[3];
    const float* V1b    = (const float*)d_in[4];
    const float* RH     = (const float*)d_in[5];
    const float* bw     = (const float*)d_in[6];
    float* out = (float*)d_out;

    cudaFuncSetAttribute(fused_gemm_kernel,
                         cudaFuncAttributeMaxDynamicSharedMemorySize, SM_TOTAL);

    // 1) Merged conversion: A split + W transpose/split in ONE launch
    conv_kernel<<<NA_BLOCKS + 2 * NW_TILES, 256>>>(hidden, K1w, V1w);

    // 2) Fused tensor-core GEMM (R14/R16 config)
    {
        dim3 gg(NH, MM / 64);  // (12, 128) = 1536 CTAs
        fused_gemm_kernel<<<gg, 256, SM_TOTAL>>>(K1b, V1b, RH);
    }

    // 3) Mask scan -> compact cnt/e/E
    scan_kernel<<<BSZ * NH, 256>>>();

    // 4) Gather + weighted sum (8 threads/tuple, uint4 rows)
    gather_kernel<<<BSZ * NH * (LEN / 32), 256>>>(bw, out);
}